// round 11
// baseline (speedup 1.0000x reference)
#include <cuda_runtime.h>
#include <cuda_bf16.h>
#include <cuda_fp16.h>
#include <cstdint>
#include <cstddef>

// ===========================================================================
// RelativeAttention on sm_100 (plain target: legacy mma.sync / HMMA).
// R11: SIM/OUT use 256x128 block tiles, 64x64 warp tiles (8 warps, 1 CTA/SM)
//      to cut cross-warp LDSM redundancy (crossbar-bound per R8/R10 evidence).
//
//   1) split x, anchors -> bf16 hi/lo; transpose+split Wq, Wk; values -> Vt fp16
//   2) Qf = x @ Wq, Kf = anchors @ Wk    (3-term bf16 mma, 128x128, 2 CTA/SM)
//   3) l2norm rows: Q -> fp16 hi/lo of 1024*qhat (+den=0), K -> fp16
//   4) SIM (2-term fp16, 256x128): acc*2^-10 -> quant->exp -> E fp16 + rowsum
//   5) OUT (1-term fp16, 256x128): O = E @ Vt^T -> scale 1/den -> fp32 out
// ===========================================================================

// ------------------------- device scratch ----------------------------------
__device__ float g_Qf[16384 * 512];
__device__ float g_Kf[4096 * 512];
__device__ float g_den[16384];
__device__ __nv_bfloat16 g_xhi[16384 * 512];
__device__ __nv_bfloat16 g_xlo[16384 * 512];
__device__ __nv_bfloat16 g_ahi[4096 * 512];
__device__ __nv_bfloat16 g_alo[4096 * 512];
__device__ __nv_bfloat16 g_Wqthi[512 * 512];
__device__ __nv_bfloat16 g_Wqtlo[512 * 512];
__device__ __nv_bfloat16 g_Wkthi[512 * 512];
__device__ __nv_bfloat16 g_Wktlo[512 * 512];
__device__ __half g_Qhi[16384 * 512];
__device__ __half g_Qlo[16384 * 512];
__device__ __half g_Kh[4096 * 512];
__device__ __half g_E[(size_t)16384 * 4096];
__device__ __half g_Vt[512 * 4096];

// ------------------------- helpers -----------------------------------------
__device__ __forceinline__ uint32_t s2u(const void* p) {
    uint32_t a;
    asm("{ .reg .u64 t; cvta.to.shared.u64 t, %1; cvt.u32.u64 %0, t; }"
        : "=r"(a) : "l"(p));
    return a;
}

__device__ __forceinline__ void cp16(uint32_t dst, const void* src) {
    asm volatile("cp.async.cg.shared.global [%0], [%1], 16;" :: "r"(dst), "l"(src));
}
#define CP_COMMIT() asm volatile("cp.async.commit_group;" ::: "memory")
#define CP_WAIT1()  asm volatile("cp.async.wait_group 1;" ::: "memory")

__device__ __forceinline__ void ldsm4(uint32_t* r, uint32_t addr) {
    asm volatile("ldmatrix.sync.aligned.m8n8.x4.shared.b16 {%0,%1,%2,%3}, [%4];"
        : "=r"(r[0]), "=r"(r[1]), "=r"(r[2]), "=r"(r[3]) : "r"(addr));
}

__device__ __forceinline__ void mma_bf16(float* d, const uint32_t* a, const uint32_t* b) {
    asm volatile(
        "mma.sync.aligned.m16n8k16.row.col.f32.bf16.bf16.f32 "
        "{%0,%1,%2,%3}, {%4,%5,%6,%7}, {%8,%9}, {%0,%1,%2,%3};"
        : "+f"(d[0]), "+f"(d[1]), "+f"(d[2]), "+f"(d[3])
        : "r"(a[0]), "r"(a[1]), "r"(a[2]), "r"(a[3]), "r"(b[0]), "r"(b[1]));
}

__device__ __forceinline__ void mma_f16(float* d, const uint32_t* a, const uint32_t* b) {
    asm volatile(
        "mma.sync.aligned.m16n8k16.row.col.f32.f16.f16.f32 "
        "{%0,%1,%2,%3}, {%4,%5,%6,%7}, {%8,%9}, {%0,%1,%2,%3};"
        : "+f"(d[0]), "+f"(d[1]), "+f"(d[2]), "+f"(d[3])
        : "r"(a[0]), "r"(a[1]), "r"(a[2]), "r"(a[3]), "r"(b[0]), "r"(b[1]));
}

__device__ __forceinline__ uint32_t pack_bf2(float a, float b) {
    __nv_bfloat16 ha = __float2bfloat16(a), hb = __float2bfloat16(b);
    return (uint32_t)__bfloat16_as_ushort(ha) |
           ((uint32_t)__bfloat16_as_ushort(hb) << 16);
}
__device__ __forceinline__ uint32_t pack_h2(float a, float b) {
    __half2 h = __floats2half2_rn(a, b);
    return *(uint32_t*)&h;
}

// ------------------------- tiling constants ---------------------------------
#define ROWB 80
#define TILE128 (128 * ROWB)            // 10240
#define TILE256 (256 * ROWB)            // 20480
#define STAGE4  (4 * TILE128)           // proj: Ahi,Alo,Bhi,Blo (128x128)
#define STAGE_S (2 * TILE256 + TILE128) // sim:  Ahi,Alo (256r), B (128r) = 51200
#define STAGE_O (TILE256 + TILE128)     // out:  A (256r), B (128r)      = 30720
static constexpr int SMEM4  = 2 * STAGE4;    // 81920
static constexpr int SMEM_S = 3 * STAGE_S;   // 153600
static constexpr int SMEM_O = 3 * STAGE_O;   // 92160

// ------------------------- stage loaders ------------------------------------
__device__ __forceinline__ void load_stage4(
    uint32_t sbase, const __nv_bfloat16* Ahi, const __nv_bfloat16* Alo,
    const __nv_bfloat16* Bhi, const __nv_bfloat16* Blo,
    int bm0, int bn0, int K, int c, int tid)
{
    const __nv_bfloat16* gp[4] = { Ahi, Alo, Bhi, Blo };
    const int rb[4] = { bm0, bm0, bn0, bn0 };
    const size_t kb = (size_t)c * 32;
#pragma unroll
    for (int t = 0; t < 8; t++) {
        const int seg  = tid + t * 256;
        const int tile = seg >> 9;
        const int w    = seg & 511;
        const int row  = w >> 2;
        const int c16  = w & 3;
        const __nv_bfloat16* src = gp[tile] + (size_t)(rb[tile] + row) * K + kb + c16 * 8;
        cp16(sbase + tile * TILE128 + row * ROWB + c16 * 16, src);
    }
}

// sim: Ahi[256r] @ 0, Alo[256r] @ TILE256, B[128r] @ 2*TILE256
__device__ __forceinline__ void load_stage_s(
    uint32_t sbase, const __half* Ahi, const __half* Alo, const __half* Bk,
    int bm0, int bn0, int K, int c, int tid)
{
    const size_t kb = (size_t)c * 32;
#pragma unroll
    for (int t = 0; t < 10; t++) {
        const int u = tid + t * 256;      // 0..2559 (A:2x1024 units, B:512)
        const __half* g;
        int row; uint32_t dst;
        if (t < 4)      { g = Ahi; row = bm0 + (u >> 2);
                          dst = sbase + (u >> 2) * ROWB; }
        else if (t < 8) { const int w = u - 1024; g = Alo; row = bm0 + (w >> 2);
                          dst = sbase + TILE256 + (w >> 2) * ROWB; }
        else            { const int w = u - 2048; g = Bk;  row = bn0 + (w >> 2);
                          dst = sbase + 2 * TILE256 + (w >> 2) * ROWB; }
        const int c16 = u & 3;
        cp16(dst + c16 * 16, g + (size_t)row * K + kb + c16 * 8);
    }
}

// out: A[256r] @ 0, B[128r] @ TILE256
__device__ __forceinline__ void load_stage_o(
    uint32_t sbase, const __half* A, const __half* B,
    int bm0, int bn0, int K, int c, int tid)
{
    const size_t kb = (size_t)c * 32;
#pragma unroll
    for (int t = 0; t < 6; t++) {
        const int u = tid + t * 256;      // 0..1535 (A:1024 units, B:512)
        const __half* g;
        int row; uint32_t dst;
        if (t < 4) { g = A; row = bm0 + (u >> 2);
                     dst = sbase + (u >> 2) * ROWB; }
        else       { const int w = u - 1024; g = B; row = bn0 + (w >> 2);
                     dst = sbase + TILE256 + (w >> 2) * ROWB; }
        const int c16 = u & 3;
        cp16(dst + c16 * 16, g + (size_t)row * K + kb + c16 * 8);
    }
}

// ------------------------- 3-term bf16 projection GEMM (128x128) ------------
__global__ __launch_bounds__(256, 2)
void proj3_kernel(const __nv_bfloat16* __restrict__ Ahi,
                  const __nv_bfloat16* __restrict__ Alo,
                  const __nv_bfloat16* __restrict__ Bhi,
                  const __nv_bfloat16* __restrict__ Blo,
                  int K, int ldC,
                  float* __restrict__ Cf)
{
    extern __shared__ char sm[];
    const uint32_t sb = s2u(sm);
    const int tid  = threadIdx.x;
    const int wid  = tid >> 5;
    const int lane = tid & 31;
    const int wm   = wid >> 1;
    const int wn   = wid & 1;
    const int g    = lane >> 2;
    const int tg   = lane & 3;
    const int bm0  = blockIdx.y * 128;
    const int bn0  = blockIdx.x * 128;

    const int grp  = lane >> 3;
    const int lrow = lane & 7;
    const uint32_t a_off = (uint32_t)((wm * 32 + lrow + ((grp & 1) << 3)) * ROWB
                                      + ((grp >> 1) << 4));
    const uint32_t b_off = (uint32_t)((wn * 64 + lrow + ((grp >> 1) << 3)) * ROWB
                                      + ((grp & 1) << 4));

    float acc[2][8][4];
#pragma unroll
    for (int mt = 0; mt < 2; mt++)
#pragma unroll
        for (int nt = 0; nt < 8; nt++)
#pragma unroll
            for (int j = 0; j < 4; j++) acc[mt][nt][j] = 0.f;

    const int nch = K >> 5;
    load_stage4(sb,          Ahi, Alo, Bhi, Blo, bm0, bn0, K, 0, tid);
    CP_COMMIT();
    load_stage4(sb + STAGE4, Ahi, Alo, Bhi, Blo, bm0, bn0, K, 1, tid);
    CP_COMMIT();

    for (int c = 0; c < nch; c++) {
        CP_WAIT1();
        __syncthreads();
        const uint32_t st = sb + (c & 1) * STAGE4;

#pragma unroll
        for (int ks = 0; ks < 2; ks++) {
            const uint32_t kk = ks * 32;
            uint32_t ah[2][4], al[2][4], bh[4][4], bl[4][4];
#pragma unroll
            for (int mt = 0; mt < 2; mt++) {
                ldsm4(ah[mt], st + a_off + mt * (16 * ROWB) + kk);
                ldsm4(al[mt], st + TILE128 + a_off + mt * (16 * ROWB) + kk);
            }
#pragma unroll
            for (int np = 0; np < 4; np++) {
                ldsm4(bh[np], st + 2 * TILE128 + b_off + np * (16 * ROWB) + kk);
                ldsm4(bl[np], st + 3 * TILE128 + b_off + np * (16 * ROWB) + kk);
            }
#pragma unroll
            for (int np = 0; np < 4; np++)
#pragma unroll
                for (int sub = 0; sub < 2; sub++)
#pragma unroll
                    for (int mt = 0; mt < 2; mt++) {
                        mma_bf16(acc[mt][np * 2 + sub], ah[mt], &bh[np][2 * sub]);
                        mma_bf16(acc[mt][np * 2 + sub], ah[mt], &bl[np][2 * sub]);
                        mma_bf16(acc[mt][np * 2 + sub], al[mt], &bh[np][2 * sub]);
                    }
        }
        __syncthreads();
        if (c + 2 < nch)
            load_stage4(sb + (c & 1) * STAGE4, Ahi, Alo, Bhi, Blo, bm0, bn0, K, c + 2, tid);
        CP_COMMIT();
    }

#pragma unroll
    for (int mt = 0; mt < 2; mt++) {
        const int rh = bm0 + wm * 32 + mt * 16 + g;
        const int rl = rh + 8;
#pragma unroll
        for (int nt = 0; nt < 8; nt++) {
            const int col = bn0 + wn * 64 + nt * 8 + tg * 2;
            *(float2*)(Cf + (size_t)rh * ldC + col) =
                make_float2(acc[mt][nt][0], acc[mt][nt][1]);
            *(float2*)(Cf + (size_t)rl * ldC + col) =
                make_float2(acc[mt][nt][2], acc[mt][nt][3]);
        }
    }
}

// ------------------------- 2-term fp16 SIM kernel (256x128) -----------------
// S*1024 = Ahi@B^T + Alo@B^T; epilogue: *2^-10 -> quant->exp -> E + rowsum.
// 8 warps 4x2, warp tile 64x64, 1 CTA/SM, 3-stage.
__global__ __launch_bounds__(256, 1)
void sim2_kernel(const __half* __restrict__ Ahi,
                 const __half* __restrict__ Alo,
                 const __half* __restrict__ Bk,
                 int K, int ldC,
                 float* __restrict__ den,
                 __half* __restrict__ E)
{
    extern __shared__ char sm[];
    const uint32_t sb = s2u(sm);
    const int tid  = threadIdx.x;
    const int wid  = tid >> 5;
    const int lane = tid & 31;
    const int wm   = wid >> 1;          // 0..3 (M, 64 rows each)
    const int wn   = wid & 1;           // 0..1 (N, 64 cols each)
    const int g    = lane >> 2;
    const int tg   = lane & 3;
    const int bm0  = blockIdx.y * 256;
    const int bn0  = blockIdx.x * 128;

    const int grp  = lane >> 3;
    const int lrow = lane & 7;
    const uint32_t a_off = (uint32_t)((wm * 64 + lrow + ((grp & 1) << 3)) * ROWB
                                      + ((grp >> 1) << 4));
    const uint32_t b_off = (uint32_t)((wn * 64 + lrow + ((grp >> 1) << 3)) * ROWB
                                      + ((grp & 1) << 4));

    float acc[4][8][4];
#pragma unroll
    for (int mt = 0; mt < 4; mt++)
#pragma unroll
        for (int nt = 0; nt < 8; nt++)
#pragma unroll
            for (int j = 0; j < 4; j++) acc[mt][nt][j] = 0.f;

    const int nch = K >> 5;   // 16
    load_stage_s(sb,           Ahi, Alo, Bk, bm0, bn0, K, 0, tid);
    CP_COMMIT();
    load_stage_s(sb + STAGE_S, Ahi, Alo, Bk, bm0, bn0, K, 1, tid);
    CP_COMMIT();

    int stg = 0, wstg = 2;
    for (int c = 0; c < nch; c++) {
        CP_WAIT1();
        __syncthreads();
        if (c + 2 < nch)
            load_stage_s(sb + wstg * STAGE_S, Ahi, Alo, Bk, bm0, bn0, K, c + 2, tid);
        CP_COMMIT();

        const uint32_t st = sb + stg * STAGE_S;
#pragma unroll
        for (int ks = 0; ks < 2; ks++) {
            const uint32_t kk = ks * 32;
            uint32_t ah[4][4], al[4][4], bh[4][4];
#pragma unroll
            for (int mt = 0; mt < 4; mt++)
                ldsm4(ah[mt], st + a_off + mt * (16 * ROWB) + kk);
#pragma unroll
            for (int mt = 0; mt < 4; mt++)
                ldsm4(al[mt], st + TILE256 + a_off + mt * (16 * ROWB) + kk);
#pragma unroll
            for (int np = 0; np < 4; np++)
                ldsm4(bh[np], st + 2 * TILE256 + b_off + np * (16 * ROWB) + kk);
#pragma unroll
            for (int np = 0; np < 4; np++)
#pragma unroll
                for (int sub = 0; sub < 2; sub++)
#pragma unroll
                    for (int mt = 0; mt < 4; mt++)
                        mma_f16(acc[mt][np * 2 + sub], ah[mt], &bh[np][2 * sub]);
#pragma unroll
            for (int np = 0; np < 4; np++)
#pragma unroll
                for (int sub = 0; sub < 2; sub++)
#pragma unroll
                    for (int mt = 0; mt < 4; mt++)
                        mma_f16(acc[mt][np * 2 + sub], al[mt], &bh[np][2 * sub]);
        }
        stg  = (stg  == 2) ? 0 : stg + 1;
        wstg = (wstg == 2) ? 0 : wstg + 1;
    }

    // epilogue: undo x1024 (exact), quantize -> exp -> E fp16 + rowsum atomics
    const float inv = 9.765625e-4f;  // 2^-10
#pragma unroll
    for (int mt = 0; mt < 4; mt++) {
        const int rh = bm0 + wm * 64 + mt * 16 + g;
        const int rl = rh + 8;
        float rs0 = 0.f, rs1 = 0.f;
#pragma unroll
        for (int nt = 0; nt < 8; nt++) {
            const int col = bn0 + wn * 64 + nt * 8 + tg * 2;
            float e0 = __expf(rintf((acc[mt][nt][0] * inv) / 0.05f) * 0.05f);
            float e1 = __expf(rintf((acc[mt][nt][1] * inv) / 0.05f) * 0.05f);
            float e2 = __expf(rintf((acc[mt][nt][2] * inv) / 0.05f) * 0.05f);
            float e3 = __expf(rintf((acc[mt][nt][3] * inv) / 0.05f) * 0.05f);
            rs0 += e0 + e1;
            rs1 += e2 + e3;
            *(uint32_t*)(E + (size_t)rh * ldC + col) = pack_h2(e0, e1);
            *(uint32_t*)(E + (size_t)rl * ldC + col) = pack_h2(e2, e3);
        }
        float v0 = rs0, v1 = rs1;
        v0 += __shfl_xor_sync(0xffffffffu, v0, 1);
        v0 += __shfl_xor_sync(0xffffffffu, v0, 2);
        v1 += __shfl_xor_sync(0xffffffffu, v1, 1);
        v1 += __shfl_xor_sync(0xffffffffu, v1, 2);
        if (tg == 0) {
            atomicAdd(&den[rh], v0);
            atomicAdd(&den[rl], v1);
        }
    }
}

// ------------------------- 1-term fp16 OUT kernel (256x128) -----------------
__global__ __launch_bounds__(256, 1)
void out1_kernel(const __half* __restrict__ E,
                 const __half* __restrict__ Vt,
                 int K, int ldC,
                 const float* __restrict__ den,
                 float* __restrict__ Cf)
{
    extern __shared__ char sm[];
    const uint32_t sb = s2u(sm);
    const int tid  = threadIdx.x;
    const int wid  = tid >> 5;
    const int lane = tid & 31;
    const int wm   = wid >> 1;
    const int wn   = wid & 1;
    const int g    = lane >> 2;
    const int tg   = lane & 3;
    const int bm0  = blockIdx.y * 256;
    const int bn0  = blockIdx.x * 128;

    const int grp  = lane >> 3;
    const int lrow = lane & 7;
    const uint32_t a_off = (uint32_t)((wm * 64 + lrow + ((grp & 1) << 3)) * ROWB
                                      + ((grp >> 1) << 4));
    const uint32_t b_off = (uint32_t)((wn * 64 + lrow + ((grp >> 1) << 3)) * ROWB
                                      + ((grp & 1) << 4));

    float acc[4][8][4];
#pragma unroll
    for (int mt = 0; mt < 4; mt++)
#pragma unroll
        for (int nt = 0; nt < 8; nt++)
#pragma unroll
            for (int j = 0; j < 4; j++) acc[mt][nt][j] = 0.f;

    const int nch = K >> 5;   // 128
    load_stage_o(sb,           E, Vt, bm0, bn0, K, 0, tid);
    CP_COMMIT();
    load_stage_o(sb + STAGE_O, E, Vt, bm0, bn0, K, 1, tid);
    CP_COMMIT();

    int stg = 0, wstg = 2;
    for (int c = 0; c < nch; c++) {
        CP_WAIT1();
        __syncthreads();
        if (c + 2 < nch)
            load_stage_o(sb + wstg * STAGE_O, E, Vt, bm0, bn0, K, c + 2, tid);
        CP_COMMIT();

        const uint32_t st = sb + stg * STAGE_O;
#pragma unroll
        for (int ks = 0; ks < 2; ks++) {
            const uint32_t kk = ks * 32;
            uint32_t ah[4][4], bh[4][4];
#pragma unroll
            for (int mt = 0; mt < 4; mt++)
                ldsm4(ah[mt], st + a_off + mt * (16 * ROWB) + kk);
#pragma unroll
            for (int np = 0; np < 4; np++)
                ldsm4(bh[np], st + TILE256 + b_off + np * (16 * ROWB) + kk);
#pragma unroll
            for (int np = 0; np < 4; np++)
#pragma unroll
                for (int sub = 0; sub < 2; sub++)
#pragma unroll
                    for (int mt = 0; mt < 4; mt++)
                        mma_f16(acc[mt][np * 2 + sub], ah[mt], &bh[np][2 * sub]);
        }
        stg  = (stg  == 2) ? 0 : stg + 1;
        wstg = (wstg == 2) ? 0 : wstg + 1;
    }

#pragma unroll
    for (int mt = 0; mt < 4; mt++) {
        const int rh = bm0 + wm * 64 + mt * 16 + g;
        const int rl = rh + 8;
        const float sh = 1.0f / den[rh];
        const float sl = 1.0f / den[rl];
#pragma unroll
        for (int nt = 0; nt < 8; nt++) {
            const int col = bn0 + wn * 64 + nt * 8 + tg * 2;
            *(float2*)(Cf + (size_t)rh * ldC + col) =
                make_float2(acc[mt][nt][0] * sh, acc[mt][nt][1] * sh);
            *(float2*)(Cf + (size_t)rl * ldC + col) =
                make_float2(acc[mt][nt][2] * sl, acc[mt][nt][3] * sl);
        }
    }
}

// ------------------------- split fp32 -> bf16 hi/lo -------------------------
__global__ void split_kernel(const float* __restrict__ s,
                             __nv_bfloat16* __restrict__ hi,
                             __nv_bfloat16* __restrict__ lo, int n4)
{
    const int i = blockIdx.x * blockDim.x + threadIdx.x;
    if (i >= n4) return;
    float4 v = ((const float4*)s)[i];
    const float f[4] = { v.x, v.y, v.z, v.w };
    uint32_t hp[2], lp[2];
#pragma unroll
    for (int j = 0; j < 2; j++) {
        __nv_bfloat16 h0 = __float2bfloat16(f[2 * j]);
        __nv_bfloat16 h1 = __float2bfloat16(f[2 * j + 1]);
        hp[j] = (uint32_t)__bfloat16_as_ushort(h0) |
                ((uint32_t)__bfloat16_as_ushort(h1) << 16);
        lp[j] = pack_bf2(f[2 * j]     - __bfloat162float(h0),
                         f[2 * j + 1] - __bfloat162float(h1));
    }
    *(uint2*)(hi + (size_t)i * 4) = make_uint2(hp[0], hp[1]);
    *(uint2*)(lo + (size_t)i * 4) = make_uint2(lp[0], lp[1]);
}

// ----------------- transpose + split: src[R,C] -> out[C,R] bf16 hi/lo -------
__global__ void trans_split_kernel(const float* __restrict__ src,
                                   __nv_bfloat16* __restrict__ hi,
                                   __nv_bfloat16* __restrict__ lo,
                                   int R, int C)
{
    __shared__ float t[32][33];
    const int c0 = blockIdx.x * 32, r0 = blockIdx.y * 32;
    const int tx = threadIdx.x, ty = threadIdx.y;   // 32 x 8
#pragma unroll
    for (int j = 0; j < 32; j += 8)
        t[ty + j][tx] = src[(size_t)(r0 + ty + j) * C + c0 + tx];
    __syncthreads();
#pragma unroll
    for (int j = 0; j < 32; j += 8) {
        const float v = t[tx][ty + j];
        __nv_bfloat16 h = __float2bfloat16(v);
        const size_t o = (size_t)(c0 + ty + j) * R + r0 + tx;
        hi[o] = h;
        lo[o] = __float2bfloat16(v - __bfloat162float(h));
    }
}

// ----------------- transpose: src[R,C] fp32 -> out[C,R] fp16 ----------------
__global__ void trans_half_kernel(const float* __restrict__ src,
                                  __half* __restrict__ dst,
                                  int R, int C)
{
    __shared__ float t[32][33];
    const int c0 = blockIdx.x * 32, r0 = blockIdx.y * 32;
    const int tx = threadIdx.x, ty = threadIdx.y;   // 32 x 8
#pragma unroll
    for (int j = 0; j < 32; j += 8)
        t[ty + j][tx] = src[(size_t)(r0 + ty + j) * C + c0 + tx];
    __syncthreads();
#pragma unroll
    for (int j = 0; j < 32; j += 8)
        dst[(size_t)(c0 + ty + j) * R + r0 + tx] = __float2half_rn(t[tx][ty + j]);
}

// ------------------------- l2 normalize variants ----------------------------
__global__ void l2norm_split_h_kernel(const float* __restrict__ P,
                                      __half* __restrict__ hi,
                                      __half* __restrict__ lo,
                                      float* __restrict__ den)
{
    const int r = blockIdx.x;
    const int t = threadIdx.x;  // 128 threads x float4 (H=512)
    const float4 v = ((const float4*)(P + (size_t)r * 512))[t];
    float ss = v.x * v.x + v.y * v.y + v.z * v.z + v.w * v.w;
#pragma unroll
    for (int m = 16; m; m >>= 1) ss += __shfl_xor_sync(0xffffffffu, ss, m);
    __shared__ float ws[4];
    if ((t & 31) == 0) ws[t >> 5] = ss;
    __syncthreads();
    const float d = fmaxf(sqrtf(ws[0] + ws[1] + ws[2] + ws[3]), 1e-12f);
    const float s = 1024.0f / d;
    const float f[4] = { v.x * s, v.y * s, v.z * s, v.w * s };
    uint32_t hp[2], lp[2];
#pragma unroll
    for (int j = 0; j < 2; j++) {
        const float a = f[2 * j], b = f[2 * j + 1];
        __half h0 = __float2half_rn(a), h1 = __float2half_rn(b);
        __half2 hh; hh.x = h0; hh.y = h1;
        hp[j] = *(uint32_t*)&hh;
        lp[j] = pack_h2(a - __half2float(h0), b - __half2float(h1));
    }
    const size_t off = (size_t)r * 512 + t * 4;
    *(uint2*)(hi + off) = make_uint2(hp[0], hp[1]);
    *(uint2*)(lo + off) = make_uint2(lp[0], lp[1]);
    if (t == 0) den[r] = 0.f;
}

__global__ void l2norm_h_kernel(const float* __restrict__ P,
                                __half* __restrict__ dst)
{
    const int r = blockIdx.x;
    const int t = threadIdx.x;
    const float4 v = ((const float4*)(P + (size_t)r * 512))[t];
    float ss = v.x * v.x + v.y * v.y + v.z * v.z + v.w * v.w;
#pragma unroll
    for (int m = 16; m; m >>= 1) ss += __shfl_xor_sync(0xffffffffu, ss, m);
    __shared__ float ws[4];
    if ((t & 31) == 0) ws[t >> 5] = ss;
    __syncthreads();
    const float d = fmaxf(sqrtf(ws[0] + ws[1] + ws[2] + ws[3]), 1e-12f);
    uint32_t hp[2];
    hp[0] = pack_h2(v.x / d, v.y / d);
    hp[1] = pack_h2(v.z / d, v.w / d);
    *(uint2*)(dst + (size_t)r * 512 + t * 4) = make_uint2(hp[0], hp[1]);
}

// ------------------------- launch -------------------------------------------
extern "C" void kernel_launch(void* const* d_in, const int* in_sizes, int n_in,
                              void* d_out, int out_size)
{
    const float* x       = (const float*)d_in[0];
    const float* anchors = (const float*)d_in[1];
    const float* Wq      = (const float*)d_in[2];
    const float* Wk      = (const float*)d_in[3];
    const float* values  = (const float*)d_in[4];
    float* out = (float*)d_out;

    const int D = 512, H = 512;
    const int B = in_sizes[0] / D;   // 16384
    const int A = in_sizes[1] / D;   // 4096

    float *Qf, *Kf, *dn;
    __nv_bfloat16 *xhi, *xlo, *ahi, *alo, *Wqthi, *Wqtlo, *Wkthi, *Wktlo;
    __half *Qhi, *Qlo, *Kh, *E, *Vt;
    cudaGetSymbolAddress((void**)&Qf,    g_Qf);
    cudaGetSymbolAddress((void**)&Kf,    g_Kf);
    cudaGetSymbolAddress((void**)&dn,    g_den);
    cudaGetSymbolAddress((void**)&xhi,   g_xhi);
    cudaGetSymbolAddress((void**)&xlo,   g_xlo);
    cudaGetSymbolAddress((void**)&ahi,   g_ahi);
    cudaGetSymbolAddress((void**)&alo,   g_alo);
    cudaGetSymbolAddress((void**)&Wqthi, g_Wqthi);
    cudaGetSymbolAddress((void**)&Wqtlo, g_Wqtlo);
    cudaGetSymbolAddress((void**)&Wkthi, g_Wkthi);
    cudaGetSymbolAddress((void**)&Wktlo, g_Wktlo);
    cudaGetSymbolAddress((void**)&Qhi,   g_Qhi);
    cudaGetSymbolAddress((void**)&Qlo,   g_Qlo);
    cudaGetSymbolAddress((void**)&Kh,    g_Kh);
    cudaGetSymbolAddress((void**)&E,     g_E);
    cudaGetSymbolAddress((void**)&Vt,    g_Vt);

    cudaFuncSetAttribute(proj3_kernel,
                         cudaFuncAttributeMaxDynamicSharedMemorySize, SMEM4);
    cudaFuncSetAttribute(sim2_kernel,
                         cudaFuncAttributeMaxDynamicSharedMemorySize, SMEM_S);
    cudaFuncSetAttribute(out1_kernel,
                         cudaFuncAttributeMaxDynamicSharedMemorySize, SMEM_O);

    // 1) splits / transposes
    split_kernel<<<(B * D / 4 + 255) / 256, 256>>>(x, xhi, xlo, B * D / 4);
    split_kernel<<<(A * D / 4 + 255) / 256, 256>>>(anchors, ahi, alo, A * D / 4);
    trans_split_kernel<<<dim3(H / 32, D / 32), dim3(32, 8)>>>(Wq, Wqthi, Wqtlo, D, H);
    trans_split_kernel<<<dim3(H / 32, D / 32), dim3(32, 8)>>>(Wk, Wkthi, Wktlo, D, H);
    trans_half_kernel<<<dim3(H / 32, A / 32), dim3(32, 8)>>>(values, Vt, A, H);

    // 2) projections (3-term bf16 mma, fp32 store)
    proj3_kernel<<<dim3(H / 128, B / 128), 256, SMEM4>>>(
        xhi, xlo, Wqthi, Wqtlo, D, H, Qf);
    proj3_kernel<<<dim3(H / 128, A / 128), 256, SMEM4>>>(
        ahi, alo, Wkthi, Wktlo, D, H, Kf);

    // 3) l2 normalize: Q -> fp16 hi/lo of 1024*qhat (+den=0), K -> fp16
    l2norm_split_h_kernel<<<B, 128>>>(Qf, Qhi, Qlo, dn);
    l2norm_h_kernel<<<A, 128>>>(Kf, Kh);

    // 4) SIM: E = exp(quant(Qn @ Kn^T)) fp16, den = rowsum (2-term fp16)
    sim2_kernel<<<dim3(A / 128, B / 256), 256, SMEM_S>>>(
        Qhi, Qlo, Kh, H, A, dn, E);

    // 5) OUT: out = (E @ V) / den  (1-term fp16)
    out1_kernel<<<dim3(H / 128, B / 256), 256, SMEM_O>>>(
        E, Vt, A, H, dn, out);
}

// round 12
// speedup vs baseline: 1.1963x; 1.1963x over previous
#include <cuda_runtime.h>
#include <cuda_bf16.h>
#include <cuda_fp16.h>
#include <cstdint>
#include <cstddef>

// ===========================================================================
// RelativeAttention on sm_100 (plain target: legacy mma.sync / HMMA).
// R12: revert to R9 GEMM configs (128x128, 2 CTA/SM, 2-stage) + merged
//      projection launch (x||anchors one grid), merged l2norm, merged split.
//
//   1) split {x, anchors} -> bf16 hi/lo (one launch); transpose+split Wq, Wk;
//      values -> Vt fp16
//   2) {Qf, Kf} = {x@Wq, anchors@Wk}   (ONE 3-term bf16 mma launch)
//   3) l2norm (one launch): Q -> fp16 hi/lo of 1024*qhat (+den=0); K -> fp16
//   4) SIM (2-term fp16): acc*2^-10 -> quant->exp -> E fp16 + rowsum atomics
//   5) OUT (1-term fp16): O = E @ Vt^T -> scale 1/den -> fp32 out
// ===========================================================================

// ------------------------- device scratch ----------------------------------
__device__ float g_Qf[16384 * 512];
__device__ float g_Kf[4096 * 512];
__device__ float g_den[16384];
__device__ __nv_bfloat16 g_xhi[16384 * 512];
__device__ __nv_bfloat16 g_xlo[16384 * 512];
__device__ __nv_bfloat16 g_ahi[4096 * 512];
__device__ __nv_bfloat16 g_alo[4096 * 512];
__device__ __nv_bfloat16 g_Wqthi[512 * 512];
__device__ __nv_bfloat16 g_Wqtlo[512 * 512];
__device__ __nv_bfloat16 g_Wkthi[512 * 512];
__device__ __nv_bfloat16 g_Wktlo[512 * 512];
__device__ __half g_Qhi[16384 * 512];
__device__ __half g_Qlo[16384 * 512];
__device__ __half g_Kh[4096 * 512];
__device__ __half g_E[(size_t)16384 * 4096];
__device__ __half g_Vt[512 * 4096];

// ------------------------- helpers -----------------------------------------
__device__ __forceinline__ uint32_t s2u(const void* p) {
    uint32_t a;
    asm("{ .reg .u64 t; cvta.to.shared.u64 t, %1; cvt.u32.u64 %0, t; }"
        : "=r"(a) : "l"(p));
    return a;
}

__device__ __forceinline__ void cp16(uint32_t dst, const void* src) {
    asm volatile("cp.async.cg.shared.global [%0], [%1], 16;" :: "r"(dst), "l"(src));
}
#define CP_COMMIT() asm volatile("cp.async.commit_group;" ::: "memory")
#define CP_WAIT1()  asm volatile("cp.async.wait_group 1;" ::: "memory")

__device__ __forceinline__ void ldsm4(uint32_t* r, uint32_t addr) {
    asm volatile("ldmatrix.sync.aligned.m8n8.x4.shared.b16 {%0,%1,%2,%3}, [%4];"
        : "=r"(r[0]), "=r"(r[1]), "=r"(r[2]), "=r"(r[3]) : "r"(addr));
}

__device__ __forceinline__ void mma_bf16(float* d, const uint32_t* a, const uint32_t* b) {
    asm volatile(
        "mma.sync.aligned.m16n8k16.row.col.f32.bf16.bf16.f32 "
        "{%0,%1,%2,%3}, {%4,%5,%6,%7}, {%8,%9}, {%0,%1,%2,%3};"
        : "+f"(d[0]), "+f"(d[1]), "+f"(d[2]), "+f"(d[3])
        : "r"(a[0]), "r"(a[1]), "r"(a[2]), "r"(a[3]), "r"(b[0]), "r"(b[1]));
}

__device__ __forceinline__ void mma_f16(float* d, const uint32_t* a, const uint32_t* b) {
    asm volatile(
        "mma.sync.aligned.m16n8k16.row.col.f32.f16.f16.f32 "
        "{%0,%1,%2,%3}, {%4,%5,%6,%7}, {%8,%9}, {%0,%1,%2,%3};"
        : "+f"(d[0]), "+f"(d[1]), "+f"(d[2]), "+f"(d[3])
        : "r"(a[0]), "r"(a[1]), "r"(a[2]), "r"(a[3]), "r"(b[0]), "r"(b[1]));
}

__device__ __forceinline__ uint32_t pack_bf2(float a, float b) {
    __nv_bfloat16 ha = __float2bfloat16(a), hb = __float2bfloat16(b);
    return (uint32_t)__bfloat16_as_ushort(ha) |
           ((uint32_t)__bfloat16_as_ushort(hb) << 16);
}
__device__ __forceinline__ uint32_t pack_h2(float a, float b) {
    __half2 h = __floats2half2_rn(a, b);
    return *(uint32_t*)&h;
}

// ------------------------- tiling constants ---------------------------------
// 128x128x32 block tile, 256 threads, 8 warps (4 M x 2 N), warp tile 32x64.
#define ROWB 80
#define TILEB (128 * ROWB)              // 10240 per tile
#define STAGE4 (4 * TILEB)              // proj: Ahi,Alo,Bhi,Blo
#define STAGE3T (3 * TILEB)             // sim:  Ahi,Alo,B
#define STAGE2T (2 * TILEB)             // out:  A,B
static constexpr int SMEM4  = 2 * STAGE4;    // 81920
static constexpr int SMEM3T = 2 * STAGE3T;   // 61440
static constexpr int SMEM2T = 2 * STAGE2T;   // 40960

// ------------------------- stage loaders ------------------------------------
__device__ __forceinline__ void load_stage4(
    uint32_t sbase, const __nv_bfloat16* Ahi, const __nv_bfloat16* Alo,
    const __nv_bfloat16* Bhi, const __nv_bfloat16* Blo,
    int bm0, int bn0, int K, int c, int tid)
{
    const __nv_bfloat16* gp[4] = { Ahi, Alo, Bhi, Blo };
    const int rb[4] = { bm0, bm0, bn0, bn0 };
    const size_t kb = (size_t)c * 32;
#pragma unroll
    for (int t = 0; t < 8; t++) {
        const int seg  = tid + t * 256;
        const int tile = seg >> 9;
        const int w    = seg & 511;
        const int row  = w >> 2;
        const int c16  = w & 3;
        const __nv_bfloat16* src = gp[tile] + (size_t)(rb[tile] + row) * K + kb + c16 * 8;
        cp16(sbase + tile * TILEB + row * ROWB + c16 * 16, src);
    }
}

__device__ __forceinline__ void load_stage3(
    uint32_t sbase, const __half* Ahi, const __half* Alo, const __half* B,
    int bm0, int bn0, int K, int c, int tid)
{
    const __half* gp[3] = { Ahi, Alo, B };
    const int rb[3] = { bm0, bm0, bn0 };
    const size_t kb = (size_t)c * 32;
#pragma unroll
    for (int t = 0; t < 6; t++) {
        const int seg  = tid + t * 256;
        const int tile = seg >> 9;
        const int w    = seg & 511;
        const int row  = w >> 2;
        const int c16  = w & 3;
        const __half* src = gp[tile] + (size_t)(rb[tile] + row) * K + kb + c16 * 8;
        cp16(sbase + tile * TILEB + row * ROWB + c16 * 16, src);
    }
}

__device__ __forceinline__ void load_stage2(
    uint32_t sbase, const __half* A, const __half* B,
    int bm0, int bn0, int K, int c, int tid)
{
    const __half* gp[2] = { A, B };
    const int rb[2] = { bm0, bn0 };
    const size_t kb = (size_t)c * 32;
#pragma unroll
    for (int t = 0; t < 4; t++) {
        const int seg  = tid + t * 256;
        const int tile = seg >> 9;
        const int w    = seg & 511;
        const int row  = w >> 2;
        const int c16  = w & 3;
        const __half* src = gp[tile] + (size_t)(rb[tile] + row) * K + kb + c16 * 8;
        cp16(sbase + tile * TILEB + row * ROWB + c16 * 16, src);
    }
}

// ------------------------- merged 3-term bf16 projection GEMM ---------------
// One launch computes BOTH Qf = x@Wq (blocks y < nby_x) and Kf = anchors@Wk.
__global__ __launch_bounds__(256, 2)
void proj3_dual_kernel(const __nv_bfloat16* __restrict__ Xhi,
                       const __nv_bfloat16* __restrict__ Xlo,
                       const __nv_bfloat16* __restrict__ WQhi,
                       const __nv_bfloat16* __restrict__ WQlo,
                       float* __restrict__ Cq,
                       const __nv_bfloat16* __restrict__ AHi,
                       const __nv_bfloat16* __restrict__ ALo,
                       const __nv_bfloat16* __restrict__ WKhi,
                       const __nv_bfloat16* __restrict__ WKlo,
                       float* __restrict__ Ck,
                       int nby_x, int K, int ldC)
{
    extern __shared__ char sm[];
    const uint32_t sb = s2u(sm);
    const int tid  = threadIdx.x;
    const int wid  = tid >> 5;
    const int lane = tid & 31;
    const int wm   = wid >> 1;
    const int wn   = wid & 1;
    const int g    = lane >> 2;
    const int tg   = lane & 3;

    const bool is_x = ((int)blockIdx.y < nby_x);
    const int bm0 = (is_x ? blockIdx.y : blockIdx.y - nby_x) * 128;
    const int bn0 = blockIdx.x * 128;
    const __nv_bfloat16* Ahi = is_x ? Xhi  : AHi;
    const __nv_bfloat16* Alo = is_x ? Xlo  : ALo;
    const __nv_bfloat16* Bhi = is_x ? WQhi : WKhi;
    const __nv_bfloat16* Blo = is_x ? WQlo : WKlo;
    float* Cf = is_x ? Cq : Ck;

    const int grp  = lane >> 3;
    const int lrow = lane & 7;
    const uint32_t a_off = (uint32_t)((wm * 32 + lrow + ((grp & 1) << 3)) * ROWB
                                      + ((grp >> 1) << 4));
    const uint32_t b_off = (uint32_t)((wn * 64 + lrow + ((grp >> 1) << 3)) * ROWB
                                      + ((grp & 1) << 4));

    float acc[2][8][4];
#pragma unroll
    for (int mt = 0; mt < 2; mt++)
#pragma unroll
        for (int nt = 0; nt < 8; nt++)
#pragma unroll
            for (int j = 0; j < 4; j++) acc[mt][nt][j] = 0.f;

    const int nch = K >> 5;
    load_stage4(sb,          Ahi, Alo, Bhi, Blo, bm0, bn0, K, 0, tid);
    CP_COMMIT();
    load_stage4(sb + STAGE4, Ahi, Alo, Bhi, Blo, bm0, bn0, K, 1, tid);
    CP_COMMIT();

    for (int c = 0; c < nch; c++) {
        CP_WAIT1();
        __syncthreads();
        const uint32_t st = sb + (c & 1) * STAGE4;

#pragma unroll
        for (int ks = 0; ks < 2; ks++) {
            const uint32_t kk = ks * 32;
            uint32_t ah[2][4], al[2][4], bh[4][4], bl[4][4];
#pragma unroll
            for (int mt = 0; mt < 2; mt++) {
                ldsm4(ah[mt], st + a_off + mt * (16 * ROWB) + kk);
                ldsm4(al[mt], st + TILEB + a_off + mt * (16 * ROWB) + kk);
            }
#pragma unroll
            for (int np = 0; np < 4; np++) {
                ldsm4(bh[np], st + 2 * TILEB + b_off + np * (16 * ROWB) + kk);
                ldsm4(bl[np], st + 3 * TILEB + b_off + np * (16 * ROWB) + kk);
            }
#pragma unroll
            for (int np = 0; np < 4; np++)
#pragma unroll
                for (int sub = 0; sub < 2; sub++)
#pragma unroll
                    for (int mt = 0; mt < 2; mt++) {
                        mma_bf16(acc[mt][np * 2 + sub], ah[mt], &bh[np][2 * sub]);
                        mma_bf16(acc[mt][np * 2 + sub], ah[mt], &bl[np][2 * sub]);
                        mma_bf16(acc[mt][np * 2 + sub], al[mt], &bh[np][2 * sub]);
                    }
        }
        __syncthreads();
        if (c + 2 < nch)
            load_stage4(sb + (c & 1) * STAGE4, Ahi, Alo, Bhi, Blo, bm0, bn0, K, c + 2, tid);
        CP_COMMIT();
    }

#pragma unroll
    for (int mt = 0; mt < 2; mt++) {
        const int rh = bm0 + wm * 32 + mt * 16 + g;
        const int rl = rh + 8;
#pragma unroll
        for (int nt = 0; nt < 8; nt++) {
            const int col = bn0 + wn * 64 + nt * 8 + tg * 2;
            *(float2*)(Cf + (size_t)rh * ldC + col) =
                make_float2(acc[mt][nt][0], acc[mt][nt][1]);
            *(float2*)(Cf + (size_t)rl * ldC + col) =
                make_float2(acc[mt][nt][2], acc[mt][nt][3]);
        }
    }
}

// ------------------------- 2-term fp16 SIM kernel (R9 config) ---------------
__global__ __launch_bounds__(256, 2)
void sim2_kernel(const __half* __restrict__ Ahi,
                 const __half* __restrict__ Alo,
                 const __half* __restrict__ Bk,
                 int K, int ldC,
                 float* __restrict__ den,
                 __half* __restrict__ E)
{
    extern __shared__ char sm[];
    const uint32_t sb = s2u(sm);
    const int tid  = threadIdx.x;
    const int wid  = tid >> 5;
    const int lane = tid & 31;
    const int wm   = wid >> 1;
    const int wn   = wid & 1;
    const int g    = lane >> 2;
    const int tg   = lane & 3;
    const int bm0  = blockIdx.y * 128;
    const int bn0  = blockIdx.x * 128;

    const int grp  = lane >> 3;
    const int lrow = lane & 7;
    const uint32_t a_off = (uint32_t)((wm * 32 + lrow + ((grp & 1) << 3)) * ROWB
                                      + ((grp >> 1) << 4));
    const uint32_t b_off = (uint32_t)((wn * 64 + lrow + ((grp >> 1) << 3)) * ROWB
                                      + ((grp & 1) << 4));

    float acc[2][8][4];
#pragma unroll
    for (int mt = 0; mt < 2; mt++)
#pragma unroll
        for (int nt = 0; nt < 8; nt++)
#pragma unroll
            for (int j = 0; j < 4; j++) acc[mt][nt][j] = 0.f;

    const int nch = K >> 5;   // 16
    load_stage3(sb,           Ahi, Alo, Bk, bm0, bn0, K, 0, tid);
    CP_COMMIT();
    load_stage3(sb + STAGE3T, Ahi, Alo, Bk, bm0, bn0, K, 1, tid);
    CP_COMMIT();

    for (int c = 0; c < nch; c++) {
        CP_WAIT1();
        __syncthreads();
        const uint32_t st = sb + (c & 1) * STAGE3T;

#pragma unroll
        for (int ks = 0; ks < 2; ks++) {
            const uint32_t kk = ks * 32;
            uint32_t ah[2][4], al[2][4], bh[4][4];
#pragma unroll
            for (int mt = 0; mt < 2; mt++) {
                ldsm4(ah[mt], st + a_off + mt * (16 * ROWB) + kk);
                ldsm4(al[mt], st + TILEB + a_off + mt * (16 * ROWB) + kk);
            }
#pragma unroll
            for (int np = 0; np < 4; np++)
                ldsm4(bh[np], st + 2 * TILEB + b_off + np * (16 * ROWB) + kk);
#pragma unroll
            for (int np = 0; np < 4; np++)
#pragma unroll
                for (int sub = 0; sub < 2; sub++)
#pragma unroll
                    for (int mt = 0; mt < 2; mt++)
                        mma_f16(acc[mt][np * 2 + sub], ah[mt], &bh[np][2 * sub]);
#pragma unroll
            for (int np = 0; np < 4; np++)
#pragma unroll
                for (int sub = 0; sub < 2; sub++)
#pragma unroll
                    for (int mt = 0; mt < 2; mt++)
                        mma_f16(acc[mt][np * 2 + sub], al[mt], &bh[np][2 * sub]);
        }
        __syncthreads();
        if (c + 2 < nch)
            load_stage3(sb + (c & 1) * STAGE3T, Ahi, Alo, Bk, bm0, bn0, K, c + 2, tid);
        CP_COMMIT();
    }

    // epilogue: undo x1024 (exact), quantize -> exp -> E fp16 + rowsum atomics
    const float inv = 9.765625e-4f;  // 2^-10
    float rs[2][2] = { {0.f, 0.f}, {0.f, 0.f} };
#pragma unroll
    for (int mt = 0; mt < 2; mt++) {
        const int rh = bm0 + wm * 32 + mt * 16 + g;
        const int rl = rh + 8;
#pragma unroll
        for (int nt = 0; nt < 8; nt++) {
            const int col = bn0 + wn * 64 + nt * 8 + tg * 2;
            float e0 = __expf(rintf((acc[mt][nt][0] * inv) / 0.05f) * 0.05f);
            float e1 = __expf(rintf((acc[mt][nt][1] * inv) / 0.05f) * 0.05f);
            float e2 = __expf(rintf((acc[mt][nt][2] * inv) / 0.05f) * 0.05f);
            float e3 = __expf(rintf((acc[mt][nt][3] * inv) / 0.05f) * 0.05f);
            rs[mt][0] += e0 + e1;
            rs[mt][1] += e2 + e3;
            *(uint32_t*)(E + (size_t)rh * ldC + col) = pack_h2(e0, e1);
            *(uint32_t*)(E + (size_t)rl * ldC + col) = pack_h2(e2, e3);
        }
    }
#pragma unroll
    for (int mt = 0; mt < 2; mt++)
#pragma unroll
        for (int hl = 0; hl < 2; hl++) {
            float v = rs[mt][hl];
            v += __shfl_xor_sync(0xffffffffu, v, 1);
            v += __shfl_xor_sync(0xffffffffu, v, 2);
            if (tg == 0)
                atomicAdd(&den[bm0 + wm * 32 + mt * 16 + g + hl * 8], v);
        }
}

// ------------------------- 1-term fp16 OUT kernel (R9 config) ---------------
__global__ __launch_bounds__(256, 2)
void out1_kernel(const __half* __restrict__ E,
                 const __half* __restrict__ Vt,
                 int K, int ldC,
                 const float* __restrict__ den,
                 float* __restrict__ Cf)
{
    extern __shared__ char sm[];
    const uint32_t sb = s2u(sm);
    const int tid  = threadIdx.x;
    const int wid  = tid >> 5;
    const int lane = tid & 31;
    const int wm   = wid >> 1;
    const int wn   = wid & 1;
    const int g    = lane >> 2;
    const int tg   = lane & 3;
    const int bm0  = blockIdx.y * 128;
    const int bn0  = blockIdx.x * 128;

    const int grp  = lane >> 3;
    const int lrow = lane & 7;
    const uint32_t a_off = (uint32_t)((wm * 32 + lrow + ((grp & 1) << 3)) * ROWB
                                      + ((grp >> 1) << 4));
    const uint32_t b_off = (uint32_t)((wn * 64 + lrow + ((grp >> 1) << 3)) * ROWB
                                      + ((grp & 1) << 4));

    float acc[2][8][4];
#pragma unroll
    for (int mt = 0; mt < 2; mt++)
#pragma unroll
        for (int nt = 0; nt < 8; nt++)
#pragma unroll
            for (int j = 0; j < 4; j++) acc[mt][nt][j] = 0.f;

    const int nch = K >> 5;   // 128
    load_stage2(sb,           E, Vt, bm0, bn0, K, 0, tid);
    CP_COMMIT();
    load_stage2(sb + STAGE2T, E, Vt, bm0, bn0, K, 1, tid);
    CP_COMMIT();

    for (int c = 0; c < nch; c++) {
        CP_WAIT1();
        __syncthreads();
        const uint32_t st = sb + (c & 1) * STAGE2T;

#pragma unroll
        for (int ks = 0; ks < 2; ks++) {
            const uint32_t kk = ks * 32;
            uint32_t ah[2][4], bh[4][4];
#pragma unroll
            for (int mt = 0; mt < 2; mt++)
                ldsm4(ah[mt], st + a_off + mt * (16 * ROWB) + kk);
#pragma unroll
            for (int np = 0; np < 4; np++)
                ldsm4(bh[np], st + TILEB + b_off + np * (16 * ROWB) + kk);
#pragma unroll
            for (int np = 0; np < 4; np++)
#pragma unroll
                for (int sub = 0; sub < 2; sub++)
#pragma unroll
                    for (int mt = 0; mt < 2; mt++)
                        mma_f16(acc[mt][np * 2 + sub], ah[mt], &bh[np][2 * sub]);
        }
        __syncthreads();
        if (c + 2 < nch)
            load_stage2(sb + (c & 1) * STAGE2T, E, Vt, bm0, bn0, K, c + 2, tid);
        CP_COMMIT();
    }

#pragma unroll
    for (int mt = 0; mt < 2; mt++) {
        const int rh = bm0 + wm * 32 + mt * 16 + g;
        const int rl = rh + 8;
        const float sh = 1.0f / den[rh];
        const float sl = 1.0f / den[rl];
#pragma unroll
        for (int nt = 0; nt < 8; nt++) {
            const int col = bn0 + wn * 64 + nt * 8 + tg * 2;
            *(float2*)(Cf + (size_t)rh * ldC + col) =
                make_float2(acc[mt][nt][0] * sh, acc[mt][nt][1] * sh);
            *(float2*)(Cf + (size_t)rl * ldC + col) =
                make_float2(acc[mt][nt][2] * sl, acc[mt][nt][3] * sl);
        }
    }
}

// ------------- merged split: {x, anchors} fp32 -> bf16 hi/lo ----------------
__global__ void split_dual_kernel(const float* __restrict__ x,
                                  __nv_bfloat16* __restrict__ xhi,
                                  __nv_bfloat16* __restrict__ xlo,
                                  int n4x,
                                  const float* __restrict__ a,
                                  __nv_bfloat16* __restrict__ ahi,
                                  __nv_bfloat16* __restrict__ alo,
                                  int n4a)
{
    int i = blockIdx.x * blockDim.x + threadIdx.x;
    const float* s;
    __nv_bfloat16 *hi, *lo;
    if (i < n4x) { s = x; hi = xhi; lo = xlo; }
    else {
        i -= n4x;
        if (i >= n4a) return;
        s = a; hi = ahi; lo = alo;
    }
    float4 v = ((const float4*)s)[i];
    const float f[4] = { v.x, v.y, v.z, v.w };
    uint32_t hp[2], lp[2];
#pragma unroll
    for (int j = 0; j < 2; j++) {
        __nv_bfloat16 h0 = __float2bfloat16(f[2 * j]);
        __nv_bfloat16 h1 = __float2bfloat16(f[2 * j + 1]);
        hp[j] = (uint32_t)__bfloat16_as_ushort(h0) |
                ((uint32_t)__bfloat16_as_ushort(h1) << 16);
        lp[j] = pack_bf2(f[2 * j]     - __bfloat162float(h0),
                         f[2 * j + 1] - __bfloat162float(h1));
    }
    *(uint2*)(hi + (size_t)i * 4) = make_uint2(hp[0], hp[1]);
    *(uint2*)(lo + (size_t)i * 4) = make_uint2(lp[0], lp[1]);
}

// ----------------- transpose + split: src[R,C] -> out[C,R] bf16 hi/lo -------
__global__ void trans_split_kernel(const float* __restrict__ src,
                                   __nv_bfloat16* __restrict__ hi,
                                   __nv_bfloat16* __restrict__ lo,
                                   int R, int C)
{
    __shared__ float t[32][33];
    const int c0 = blockIdx.x * 32, r0 = blockIdx.y * 32;
    const int tx = threadIdx.x, ty = threadIdx.y;   // 32 x 8
#pragma unroll
    for (int j = 0; j < 32; j += 8)
        t[ty + j][tx] = src[(size_t)(r0 + ty + j) * C + c0 + tx];
    __syncthreads();
#pragma unroll
    for (int j = 0; j < 32; j += 8) {
        const float v = t[tx][ty + j];
        __nv_bfloat16 h = __float2bfloat16(v);
        const size_t o = (size_t)(c0 + ty + j) * R + r0 + tx;
        hi[o] = h;
        lo[o] = __float2bfloat16(v - __bfloat162float(h));
    }
}

// ----------------- transpose: src[R,C] fp32 -> out[C,R] fp16 ----------------
__global__ void trans_half_kernel(const float* __restrict__ src,
                                  __half* __restrict__ dst,
                                  int R, int C)
{
    __shared__ float t[32][33];
    const int c0 = blockIdx.x * 32, r0 = blockIdx.y * 32;
    const int tx = threadIdx.x, ty = threadIdx.y;   // 32 x 8
#pragma unroll
    for (int j = 0; j < 32; j += 8)
        t[ty + j][tx] = src[(size_t)(r0 + ty + j) * C + c0 + tx];
    __syncthreads();
#pragma unroll
    for (int j = 0; j < 32; j += 8)
        dst[(size_t)(c0 + ty + j) * R + r0 + tx] = __float2half_rn(t[tx][ty + j]);
}

// ------------------------- merged l2 normalize ------------------------------
// blocks [0, B):  Q path -> fp16 hi/lo of 1024*qhat, den[r]=0
// blocks [B, B+A): K path -> single fp16 of khat
__global__ void l2norm_dual_kernel(const float* __restrict__ Qf,
                                   __half* __restrict__ Qhi,
                                   __half* __restrict__ Qlo,
                                   float* __restrict__ den,
                                   int B,
                                   const float* __restrict__ Kf,
                                   __half* __restrict__ Kh)
{
    const int blk = blockIdx.x;
    const bool isQ = (blk < B);
    const int r = isQ ? blk : blk - B;
    const float* P = isQ ? Qf : Kf;
    const int t = threadIdx.x;  // 128 threads x float4 (H=512)
    const float4 v = ((const float4*)(P + (size_t)r * 512))[t];
    float ss = v.x * v.x + v.y * v.y + v.z * v.z + v.w * v.w;
#pragma unroll
    for (int m = 16; m; m >>= 1) ss += __shfl_xor_sync(0xffffffffu, ss, m);
    __shared__ float ws[4];
    if ((t & 31) == 0) ws[t >> 5] = ss;
    __syncthreads();
    const float d = fmaxf(sqrtf(ws[0] + ws[1] + ws[2] + ws[3]), 1e-12f);
    if (isQ) {
        const float s = 1024.0f / d;
        const float f[4] = { v.x * s, v.y * s, v.z * s, v.w * s };
        uint32_t hp[2], lp[2];
#pragma unroll
        for (int j = 0; j < 2; j++) {
            const float a = f[2 * j], b = f[2 * j + 1];
            __half h0 = __float2half_rn(a), h1 = __float2half_rn(b);
            __half2 hh; hh.x = h0; hh.y = h1;
            hp[j] = *(uint32_t*)&hh;
            lp[j] = pack_h2(a - __half2float(h0), b - __half2float(h1));
        }
        const size_t off = (size_t)r * 512 + t * 4;
        *(uint2*)(Qhi + off) = make_uint2(hp[0], hp[1]);
        *(uint2*)(Qlo + off) = make_uint2(lp[0], lp[1]);
        if (t == 0) den[r] = 0.f;
    } else {
        uint32_t hp[2];
        hp[0] = pack_h2(v.x / d, v.y / d);
        hp[1] = pack_h2(v.z / d, v.w / d);
        *(uint2*)(Kh + (size_t)r * 512 + t * 4) = make_uint2(hp[0], hp[1]);
    }
}

// ------------------------- launch -------------------------------------------
extern "C" void kernel_launch(void* const* d_in, const int* in_sizes, int n_in,
                              void* d_out, int out_size)
{
    const float* x       = (const float*)d_in[0];
    const float* anchors = (const float*)d_in[1];
    const float* Wq      = (const float*)d_in[2];
    const float* Wk      = (const float*)d_in[3];
    const float* values  = (const float*)d_in[4];
    float* out = (float*)d_out;

    const int D = 512, H = 512;
    const int B = in_sizes[0] / D;   // 16384
    const int A = in_sizes[1] / D;   // 4096

    float *Qf, *Kf, *dn;
    __nv_bfloat16 *xhi, *xlo, *ahi, *alo, *Wqthi, *Wqtlo, *Wkthi, *Wktlo;
    __half *Qhi, *Qlo, *Kh, *E, *Vt;
    cudaGetSymbolAddress((void**)&Qf,    g_Qf);
    cudaGetSymbolAddress((void**)&Kf,    g_Kf);
    cudaGetSymbolAddress((void**)&dn,    g_den);
    cudaGetSymbolAddress((void**)&xhi,   g_xhi);
    cudaGetSymbolAddress((void**)&xlo,   g_xlo);
    cudaGetSymbolAddress((void**)&ahi,   g_ahi);
    cudaGetSymbolAddress((void**)&alo,   g_alo);
    cudaGetSymbolAddress((void**)&Wqthi, g_Wqthi);
    cudaGetSymbolAddress((void**)&Wqtlo, g_Wqtlo);
    cudaGetSymbolAddress((void**)&Wkthi, g_Wkthi);
    cudaGetSymbolAddress((void**)&Wktlo, g_Wktlo);
    cudaGetSymbolAddress((void**)&Qhi,   g_Qhi);
    cudaGetSymbolAddress((void**)&Qlo,   g_Qlo);
    cudaGetSymbolAddress((void**)&Kh,    g_Kh);
    cudaGetSymbolAddress((void**)&E,     g_E);
    cudaGetSymbolAddress((void**)&Vt,    g_Vt);

    cudaFuncSetAttribute(proj3_dual_kernel,
                         cudaFuncAttributeMaxDynamicSharedMemorySize, SMEM4);
    cudaFuncSetAttribute(sim2_kernel,
                         cudaFuncAttributeMaxDynamicSharedMemorySize, SMEM3T);
    cudaFuncSetAttribute(out1_kernel,
                         cudaFuncAttributeMaxDynamicSharedMemorySize, SMEM2T);

    // 1) splits / transposes
    const int n4x = B * D / 4, n4a = A * D / 4;
    split_dual_kernel<<<(n4x + n4a + 255) / 256, 256>>>(
        x, xhi, xlo, n4x, anchors, ahi, alo, n4a);
    trans_split_kernel<<<dim3(H / 32, D / 32), dim3(32, 8)>>>(Wq, Wqthi, Wqtlo, D, H);
    trans_split_kernel<<<dim3(H / 32, D / 32), dim3(32, 8)>>>(Wk, Wkthi, Wktlo, D, H);
    trans_half_kernel<<<dim3(H / 32, A / 32), dim3(32, 8)>>>(values, Vt, A, H);

    // 2) BOTH projections in one launch (x blocks then anchor blocks)
    proj3_dual_kernel<<<dim3(H / 128, B / 128 + A / 128), 256, SMEM4>>>(
        xhi, xlo, Wqthi, Wqtlo, Qf,
        ahi, alo, Wkthi, Wktlo, Kf,
        B / 128, D, H);

    // 3) merged l2 normalize (Q fp16 hi/lo x1024 + den=0; K fp16)
    l2norm_dual_kernel<<<B + A, 128>>>(Qf, Qhi, Qlo, dn, B, Kf, Kh);

    // 4) SIM: E = exp(quant(Qn @ Kn^T)) fp16, den = rowsum (2-term fp16)
    sim2_kernel<<<dim3(A / 128, B / 128), 256, SMEM3T>>>(
        Qhi, Qlo, Kh, H, A, dn, E);

    // 5) OUT: out = (E @ V) / den  (1-term fp16)
    out1_kernel<<<dim3(H / 128, B / 128), 256, SMEM2T>>>(
        E, Vt, A, H, dn, out);
}

// round 13
// speedup vs baseline: 1.4839x; 1.2404x over previous
#include <cuda_runtime.h>
#include <cuda_bf16.h>
#include <cuda_fp16.h>
#include <cstdint>
#include <cstddef>

// ===========================================================================
// RelativeAttention on sm_100 (plain target: legacy mma.sync / HMMA).
// R13: SIM reduced to ONE fp16 GEMM (Qh @ Kh^T) — error budget validated
//      empirically (K-side fp16 component measured 6.03e-4; Q symmetric).
//      Merged transpose prep launch.
//
//   1) split {x, anchors} -> bf16 hi/lo (one launch);
//      one launch transposes+splits Wq, Wk (bf16) and values -> Vt (fp16)
//   2) {Qf, Kf} = {x@Wq, anchors@Wk}   (one 3-term bf16 mma launch)
//   3) l2norm (one launch): Q -> fp16 qhat (+den=0); K -> fp16 khat
//   4) SIM (1-term fp16): quant->exp -> E fp16 + rowsum atomics
//   5) OUT (1-term fp16): O = E @ Vt^T -> scale 1/den -> fp32 out
// ===========================================================================

// ------------------------- device scratch ----------------------------------
__device__ float g_Qf[16384 * 512];
__device__ float g_Kf[4096 * 512];
__device__ float g_den[16384];
__device__ __nv_bfloat16 g_xhi[16384 * 512];
__device__ __nv_bfloat16 g_xlo[16384 * 512];
__device__ __nv_bfloat16 g_ahi[4096 * 512];
__device__ __nv_bfloat16 g_alo[4096 * 512];
__device__ __nv_bfloat16 g_Wqthi[512 * 512];
__device__ __nv_bfloat16 g_Wqtlo[512 * 512];
__device__ __nv_bfloat16 g_Wkthi[512 * 512];
__device__ __nv_bfloat16 g_Wktlo[512 * 512];
__device__ __half g_Qh[16384 * 512];
__device__ __half g_Kh[4096 * 512];
__device__ __half g_E[(size_t)16384 * 4096];
__device__ __half g_Vt[512 * 4096];

// ------------------------- helpers -----------------------------------------
__device__ __forceinline__ uint32_t s2u(const void* p) {
    uint32_t a;
    asm("{ .reg .u64 t; cvta.to.shared.u64 t, %1; cvt.u32.u64 %0, t; }"
        : "=r"(a) : "l"(p));
    return a;
}

__device__ __forceinline__ void cp16(uint32_t dst, const void* src) {
    asm volatile("cp.async.cg.shared.global [%0], [%1], 16;" :: "r"(dst), "l"(src));
}
#define CP_COMMIT() asm volatile("cp.async.commit_group;" ::: "memory")
#define CP_WAIT1()  asm volatile("cp.async.wait_group 1;" ::: "memory")

__device__ __forceinline__ void ldsm4(uint32_t* r, uint32_t addr) {
    asm volatile("ldmatrix.sync.aligned.m8n8.x4.shared.b16 {%0,%1,%2,%3}, [%4];"
        : "=r"(r[0]), "=r"(r[1]), "=r"(r[2]), "=r"(r[3]) : "r"(addr));
}

__device__ __forceinline__ void mma_bf16(float* d, const uint32_t* a, const uint32_t* b) {
    asm volatile(
        "mma.sync.aligned.m16n8k16.row.col.f32.bf16.bf16.f32 "
        "{%0,%1,%2,%3}, {%4,%5,%6,%7}, {%8,%9}, {%0,%1,%2,%3};"
        : "+f"(d[0]), "+f"(d[1]), "+f"(d[2]), "+f"(d[3])
        : "r"(a[0]), "r"(a[1]), "r"(a[2]), "r"(a[3]), "r"(b[0]), "r"(b[1]));
}

__device__ __forceinline__ void mma_f16(float* d, const uint32_t* a, const uint32_t* b) {
    asm volatile(
        "mma.sync.aligned.m16n8k16.row.col.f32.f16.f16.f32 "
        "{%0,%1,%2,%3}, {%4,%5,%6,%7}, {%8,%9}, {%0,%1,%2,%3};"
        : "+f"(d[0]), "+f"(d[1]), "+f"(d[2]), "+f"(d[3])
        : "r"(a[0]), "r"(a[1]), "r"(a[2]), "r"(a[3]), "r"(b[0]), "r"(b[1]));
}

__device__ __forceinline__ uint32_t pack_bf2(float a, float b) {
    __nv_bfloat16 ha = __float2bfloat16(a), hb = __float2bfloat16(b);
    return (uint32_t)__bfloat16_as_ushort(ha) |
           ((uint32_t)__bfloat16_as_ushort(hb) << 16);
}
__device__ __forceinline__ uint32_t pack_h2(float a, float b) {
    __half2 h = __floats2half2_rn(a, b);
    return *(uint32_t*)&h;
}

// ------------------------- tiling constants ---------------------------------
// 128x128x32 block tile, 256 threads, 8 warps (4 M x 2 N), warp tile 32x64.
#define ROWB 80
#define TILEB (128 * ROWB)              // 10240 per tile
#define STAGE4 (4 * TILEB)              // proj: Ahi,Alo,Bhi,Blo
#define STAGE2T (2 * TILEB)             // sim/out: A,B
static constexpr int SMEM4  = 2 * STAGE4;    // 81920
static constexpr int SMEM2T = 2 * STAGE2T;   // 40960

// ------------------------- stage loaders ------------------------------------
__device__ __forceinline__ void load_stage4(
    uint32_t sbase, const __nv_bfloat16* Ahi, const __nv_bfloat16* Alo,
    const __nv_bfloat16* Bhi, const __nv_bfloat16* Blo,
    int bm0, int bn0, int K, int c, int tid)
{
    const __nv_bfloat16* gp[4] = { Ahi, Alo, Bhi, Blo };
    const int rb[4] = { bm0, bm0, bn0, bn0 };
    const size_t kb = (size_t)c * 32;
#pragma unroll
    for (int t = 0; t < 8; t++) {
        const int seg  = tid + t * 256;
        const int tile = seg >> 9;
        const int w    = seg & 511;
        const int row  = w >> 2;
        const int c16  = w & 3;
        const __nv_bfloat16* src = gp[tile] + (size_t)(rb[tile] + row) * K + kb + c16 * 8;
        cp16(sbase + tile * TILEB + row * ROWB + c16 * 16, src);
    }
}

__device__ __forceinline__ void load_stage2(
    uint32_t sbase, const __half* A, const __half* B,
    int bm0, int bn0, int K, int c, int tid)
{
    const __half* gp[2] = { A, B };
    const int rb[2] = { bm0, bn0 };
    const size_t kb = (size_t)c * 32;
#pragma unroll
    for (int t = 0; t < 4; t++) {
        const int seg  = tid + t * 256;
        const int tile = seg >> 9;
        const int w    = seg & 511;
        const int row  = w >> 2;
        const int c16  = w & 3;
        const __half* src = gp[tile] + (size_t)(rb[tile] + row) * K + kb + c16 * 8;
        cp16(sbase + tile * TILEB + row * ROWB + c16 * 16, src);
    }
}

// ------------------------- merged 3-term bf16 projection GEMM ---------------
__global__ __launch_bounds__(256, 2)
void proj3_dual_kernel(const __nv_bfloat16* __restrict__ Xhi,
                       const __nv_bfloat16* __restrict__ Xlo,
                       const __nv_bfloat16* __restrict__ WQhi,
                       const __nv_bfloat16* __restrict__ WQlo,
                       float* __restrict__ Cq,
                       const __nv_bfloat16* __restrict__ AHi,
                       const __nv_bfloat16* __restrict__ ALo,
                       const __nv_bfloat16* __restrict__ WKhi,
                       const __nv_bfloat16* __restrict__ WKlo,
                       float* __restrict__ Ck,
                       int nby_x, int K, int ldC)
{
    extern __shared__ char sm[];
    const uint32_t sb = s2u(sm);
    const int tid  = threadIdx.x;
    const int wid  = tid >> 5;
    const int lane = tid & 31;
    const int wm   = wid >> 1;
    const int wn   = wid & 1;
    const int g    = lane >> 2;
    const int tg   = lane & 3;

    const bool is_x = ((int)blockIdx.y < nby_x);
    const int bm0 = (is_x ? blockIdx.y : blockIdx.y - nby_x) * 128;
    const int bn0 = blockIdx.x * 128;
    const __nv_bfloat16* Ahi = is_x ? Xhi  : AHi;
    const __nv_bfloat16* Alo = is_x ? Xlo  : ALo;
    const __nv_bfloat16* Bhi = is_x ? WQhi : WKhi;
    const __nv_bfloat16* Blo = is_x ? WQlo : WKlo;
    float* Cf = is_x ? Cq : Ck;

    const int grp  = lane >> 3;
    const int lrow = lane & 7;
    const uint32_t a_off = (uint32_t)((wm * 32 + lrow + ((grp & 1) << 3)) * ROWB
                                      + ((grp >> 1) << 4));
    const uint32_t b_off = (uint32_t)((wn * 64 + lrow + ((grp >> 1) << 3)) * ROWB
                                      + ((grp & 1) << 4));

    float acc[2][8][4];
#pragma unroll
    for (int mt = 0; mt < 2; mt++)
#pragma unroll
        for (int nt = 0; nt < 8; nt++)
#pragma unroll
            for (int j = 0; j < 4; j++) acc[mt][nt][j] = 0.f;

    const int nch = K >> 5;
    load_stage4(sb,          Ahi, Alo, Bhi, Blo, bm0, bn0, K, 0, tid);
    CP_COMMIT();
    load_stage4(sb + STAGE4, Ahi, Alo, Bhi, Blo, bm0, bn0, K, 1, tid);
    CP_COMMIT();

    for (int c = 0; c < nch; c++) {
        CP_WAIT1();
        __syncthreads();
        const uint32_t st = sb + (c & 1) * STAGE4;

#pragma unroll
        for (int ks = 0; ks < 2; ks++) {
            const uint32_t kk = ks * 32;
            uint32_t ah[2][4], al[2][4], bh[4][4], bl[4][4];
#pragma unroll
            for (int mt = 0; mt < 2; mt++) {
                ldsm4(ah[mt], st + a_off + mt * (16 * ROWB) + kk);
                ldsm4(al[mt], st + TILEB + a_off + mt * (16 * ROWB) + kk);
            }
#pragma unroll
            for (int np = 0; np < 4; np++) {
                ldsm4(bh[np], st + 2 * TILEB + b_off + np * (16 * ROWB) + kk);
                ldsm4(bl[np], st + 3 * TILEB + b_off + np * (16 * ROWB) + kk);
            }
#pragma unroll
            for (int np = 0; np < 4; np++)
#pragma unroll
                for (int sub = 0; sub < 2; sub++)
#pragma unroll
                    for (int mt = 0; mt < 2; mt++) {
                        mma_bf16(acc[mt][np * 2 + sub], ah[mt], &bh[np][2 * sub]);
                        mma_bf16(acc[mt][np * 2 + sub], ah[mt], &bl[np][2 * sub]);
                        mma_bf16(acc[mt][np * 2 + sub], al[mt], &bh[np][2 * sub]);
                    }
        }
        __syncthreads();
        if (c + 2 < nch)
            load_stage4(sb + (c & 1) * STAGE4, Ahi, Alo, Bhi, Blo, bm0, bn0, K, c + 2, tid);
        CP_COMMIT();
    }

#pragma unroll
    for (int mt = 0; mt < 2; mt++) {
        const int rh = bm0 + wm * 32 + mt * 16 + g;
        const int rl = rh + 8;
#pragma unroll
        for (int nt = 0; nt < 8; nt++) {
            const int col = bn0 + wn * 64 + nt * 8 + tg * 2;
            *(float2*)(Cf + (size_t)rh * ldC + col) =
                make_float2(acc[mt][nt][0], acc[mt][nt][1]);
            *(float2*)(Cf + (size_t)rl * ldC + col) =
                make_float2(acc[mt][nt][2], acc[mt][nt][3]);
        }
    }
}

// ------------------------- 1-term fp16 SIM kernel ---------------------------
// S = Qh @ Kh^T; epilogue: quant->exp -> E fp16 + rowsum atomics.
__global__ __launch_bounds__(256, 2)
void sim1_kernel(const __half* __restrict__ Qh,
                 const __half* __restrict__ Kh,
                 int K, int ldC,
                 float* __restrict__ den,
                 __half* __restrict__ E)
{
    extern __shared__ char sm[];
    const uint32_t sb = s2u(sm);
    const int tid  = threadIdx.x;
    const int wid  = tid >> 5;
    const int lane = tid & 31;
    const int wm   = wid >> 1;
    const int wn   = wid & 1;
    const int g    = lane >> 2;
    const int tg   = lane & 3;
    const int bm0  = blockIdx.y * 128;
    const int bn0  = blockIdx.x * 128;

    const int grp  = lane >> 3;
    const int lrow = lane & 7;
    const uint32_t a_off = (uint32_t)((wm * 32 + lrow + ((grp & 1) << 3)) * ROWB
                                      + ((grp >> 1) << 4));
    const uint32_t b_off = (uint32_t)((wn * 64 + lrow + ((grp >> 1) << 3)) * ROWB
                                      + ((grp & 1) << 4));

    float acc[2][8][4];
#pragma unroll
    for (int mt = 0; mt < 2; mt++)
#pragma unroll
        for (int nt = 0; nt < 8; nt++)
#pragma unroll
            for (int j = 0; j < 4; j++) acc[mt][nt][j] = 0.f;

    const int nch = K >> 5;   // 16
    load_stage2(sb,           Qh, Kh, bm0, bn0, K, 0, tid);
    CP_COMMIT();
    load_stage2(sb + STAGE2T, Qh, Kh, bm0, bn0, K, 1, tid);
    CP_COMMIT();

    for (int c = 0; c < nch; c++) {
        CP_WAIT1();
        __syncthreads();
        const uint32_t st = sb + (c & 1) * STAGE2T;

#pragma unroll
        for (int ks = 0; ks < 2; ks++) {
            const uint32_t kk = ks * 32;
            uint32_t ah[2][4], bh[4][4];
#pragma unroll
            for (int mt = 0; mt < 2; mt++)
                ldsm4(ah[mt], st + a_off + mt * (16 * ROWB) + kk);
#pragma unroll
            for (int np = 0; np < 4; np++)
                ldsm4(bh[np], st + TILEB + b_off + np * (16 * ROWB) + kk);
#pragma unroll
            for (int np = 0; np < 4; np++)
#pragma unroll
                for (int sub = 0; sub < 2; sub++)
#pragma unroll
                    for (int mt = 0; mt < 2; mt++)
                        mma_f16(acc[mt][np * 2 + sub], ah[mt], &bh[np][2 * sub]);
        }
        __syncthreads();
        if (c + 2 < nch)
            load_stage2(sb + (c & 1) * STAGE2T, Qh, Kh, bm0, bn0, K, c + 2, tid);
        CP_COMMIT();
    }

    // epilogue: quantize -> exp -> E fp16 + rowsum atomics
    float rs[2][2] = { {0.f, 0.f}, {0.f, 0.f} };
#pragma unroll
    for (int mt = 0; mt < 2; mt++) {
        const int rh = bm0 + wm * 32 + mt * 16 + g;
        const int rl = rh + 8;
#pragma unroll
        for (int nt = 0; nt < 8; nt++) {
            const int col = bn0 + wn * 64 + nt * 8 + tg * 2;
            float e0 = __expf(rintf(acc[mt][nt][0] / 0.05f) * 0.05f);
            float e1 = __expf(rintf(acc[mt][nt][1] / 0.05f) * 0.05f);
            float e2 = __expf(rintf(acc[mt][nt][2] / 0.05f) * 0.05f);
            float e3 = __expf(rintf(acc[mt][nt][3] / 0.05f) * 0.05f);
            rs[mt][0] += e0 + e1;
            rs[mt][1] += e2 + e3;
            *(uint32_t*)(E + (size_t)rh * ldC + col) = pack_h2(e0, e1);
            *(uint32_t*)(E + (size_t)rl * ldC + col) = pack_h2(e2, e3);
        }
    }
#pragma unroll
    for (int mt = 0; mt < 2; mt++)
#pragma unroll
        for (int hl = 0; hl < 2; hl++) {
            float v = rs[mt][hl];
            v += __shfl_xor_sync(0xffffffffu, v, 1);
            v += __shfl_xor_sync(0xffffffffu, v, 2);
            if (tg == 0)
                atomicAdd(&den[bm0 + wm * 32 + mt * 16 + g + hl * 8], v);
        }
}

// ------------------------- 1-term fp16 OUT kernel ---------------------------
__global__ __launch_bounds__(256, 2)
void out1_kernel(const __half* __restrict__ E,
                 const __half* __restrict__ Vt,
                 int K, int ldC,
                 const float* __restrict__ den,
                 float* __restrict__ Cf)
{
    extern __shared__ char sm[];
    const uint32_t sb = s2u(sm);
    const int tid  = threadIdx.x;
    const int wid  = tid >> 5;
    const int lane = tid & 31;
    const int wm   = wid >> 1;
    const int wn   = wid & 1;
    const int g    = lane >> 2;
    const int tg   = lane & 3;
    const int bm0  = blockIdx.y * 128;
    const int bn0  = blockIdx.x * 128;

    const int grp  = lane >> 3;
    const int lrow = lane & 7;
    const uint32_t a_off = (uint32_t)((wm * 32 + lrow + ((grp & 1) << 3)) * ROWB
                                      + ((grp >> 1) << 4));
    const uint32_t b_off = (uint32_t)((wn * 64 + lrow + ((grp >> 1) << 3)) * ROWB
                                      + ((grp & 1) << 4));

    float acc[2][8][4];
#pragma unroll
    for (int mt = 0; mt < 2; mt++)
#pragma unroll
        for (int nt = 0; nt < 8; nt++)
#pragma unroll
            for (int j = 0; j < 4; j++) acc[mt][nt][j] = 0.f;

    const int nch = K >> 5;   // 128
    load_stage2(sb,           E, Vt, bm0, bn0, K, 0, tid);
    CP_COMMIT();
    load_stage2(sb + STAGE2T, E, Vt, bm0, bn0, K, 1, tid);
    CP_COMMIT();

    for (int c = 0; c < nch; c++) {
        CP_WAIT1();
        __syncthreads();
        const uint32_t st = sb + (c & 1) * STAGE2T;

#pragma unroll
        for (int ks = 0; ks < 2; ks++) {
            const uint32_t kk = ks * 32;
            uint32_t ah[2][4], bh[4][4];
#pragma unroll
            for (int mt = 0; mt < 2; mt++)
                ldsm4(ah[mt], st + a_off + mt * (16 * ROWB) + kk);
#pragma unroll
            for (int np = 0; np < 4; np++)
                ldsm4(bh[np], st + TILEB + b_off + np * (16 * ROWB) + kk);
#pragma unroll
            for (int np = 0; np < 4; np++)
#pragma unroll
                for (int sub = 0; sub < 2; sub++)
#pragma unroll
                    for (int mt = 0; mt < 2; mt++)
                        mma_f16(acc[mt][np * 2 + sub], ah[mt], &bh[np][2 * sub]);
        }
        __syncthreads();
        if (c + 2 < nch)
            load_stage2(sb + (c & 1) * STAGE2T, E, Vt, bm0, bn0, K, c + 2, tid);
        CP_COMMIT();
    }

#pragma unroll
    for (int mt = 0; mt < 2; mt++) {
        const int rh = bm0 + wm * 32 + mt * 16 + g;
        const int rl = rh + 8;
        const float sh = 1.0f / den[rh];
        const float sl = 1.0f / den[rl];
#pragma unroll
        for (int nt = 0; nt < 8; nt++) {
            const int col = bn0 + wn * 64 + nt * 8 + tg * 2;
            *(float2*)(Cf + (size_t)rh * ldC + col) =
                make_float2(acc[mt][nt][0] * sh, acc[mt][nt][1] * sh);
            *(float2*)(Cf + (size_t)rl * ldC + col) =
                make_float2(acc[mt][nt][2] * sl, acc[mt][nt][3] * sl);
        }
    }
}

// ------------- merged split: {x, anchors} fp32 -> bf16 hi/lo ----------------
__global__ void split_dual_kernel(const float* __restrict__ x,
                                  __nv_bfloat16* __restrict__ xhi,
                                  __nv_bfloat16* __restrict__ xlo,
                                  int n4x,
                                  const float* __restrict__ a,
                                  __nv_bfloat16* __restrict__ ahi,
                                  __nv_bfloat16* __restrict__ alo,
                                  int n4a)
{
    int i = blockIdx.x * blockDim.x + threadIdx.x;
    const float* s;
    __nv_bfloat16 *hi, *lo;
    if (i < n4x) { s = x; hi = xhi; lo = xlo; }
    else {
        i -= n4x;
        if (i >= n4a) return;
        s = a; hi = ahi; lo = alo;
    }
    float4 v = ((const float4*)s)[i];
    const float f[4] = { v.x, v.y, v.z, v.w };
    uint32_t hp[2], lp[2];
#pragma unroll
    for (int j = 0; j < 2; j++) {
        __nv_bfloat16 h0 = __float2bfloat16(f[2 * j]);
        __nv_bfloat16 h1 = __float2bfloat16(f[2 * j + 1]);
        hp[j] = (uint32_t)__bfloat16_as_ushort(h0) |
                ((uint32_t)__bfloat16_as_ushort(h1) << 16);
        lp[j] = pack_bf2(f[2 * j]     - __bfloat162float(h0),
                         f[2 * j + 1] - __bfloat162float(h1));
    }
    *(uint2*)(hi + (size_t)i * 4) = make_uint2(hp[0], hp[1]);
    *(uint2*)(lo + (size_t)i * 4) = make_uint2(lp[0], lp[1]);
}

// ------------- merged transpose prep: Wq, Wk (bf16 split) + V (fp16) --------
// grid (16, 16 + 16 + 128); all sources are [R, 512] fp32, outputs [512, R].
__global__ void trans_all_kernel(const float* __restrict__ Wq,
                                 __nv_bfloat16* __restrict__ Wqthi,
                                 __nv_bfloat16* __restrict__ Wqtlo,
                                 const float* __restrict__ Wk,
                                 __nv_bfloat16* __restrict__ Wkthi,
                                 __nv_bfloat16* __restrict__ Wktlo,
                                 const float* __restrict__ V,
                                 __half* __restrict__ Vt)
{
    __shared__ float t[32][33];
    const int by = blockIdx.y;
    const float* src;
    __nv_bfloat16 *hi = nullptr, *lo = nullptr;
    int mode, byl, R;
    if (by < 16)       { src = Wq; hi = Wqthi; lo = Wqtlo; R = 512;  mode = 0; byl = by; }
    else if (by < 32)  { src = Wk; hi = Wkthi; lo = Wktlo; R = 512;  mode = 0; byl = by - 16; }
    else               { src = V;                          R = 4096; mode = 1; byl = by - 32; }
    const int C = 512;
    const int c0 = blockIdx.x * 32, r0 = byl * 32;
    const int tx = threadIdx.x, ty = threadIdx.y;   // 32 x 8
#pragma unroll
    for (int j = 0; j < 32; j += 8)
        t[ty + j][tx] = src[(size_t)(r0 + ty + j) * C + c0 + tx];
    __syncthreads();
    if (mode == 0) {
#pragma unroll
        for (int j = 0; j < 32; j += 8) {
            const float v = t[tx][ty + j];
            __nv_bfloat16 h = __float2bfloat16(v);
            const size_t o = (size_t)(c0 + ty + j) * R + r0 + tx;
            hi[o] = h;
            lo[o] = __float2bfloat16(v - __bfloat162float(h));
        }
    } else {
#pragma unroll
        for (int j = 0; j < 32; j += 8)
            Vt[(size_t)(c0 + ty + j) * R + r0 + tx] = __float2half_rn(t[tx][ty + j]);
    }
}

// ------------------------- merged l2 normalize ------------------------------
// blocks [0, B):  Q path -> fp16 qhat, den[r]=0
// blocks [B, B+A): K path -> fp16 khat
__global__ void l2norm_dual_kernel(const float* __restrict__ Qf,
                                   __half* __restrict__ Qh,
                                   float* __restrict__ den,
                                   int B,
                                   const float* __restrict__ Kf,
                                   __half* __restrict__ Kh)
{
    const int blk = blockIdx.x;
    const bool isQ = (blk < B);
    const int r = isQ ? blk : blk - B;
    const float* P = isQ ? Qf : Kf;
    const int t = threadIdx.x;  // 128 threads x float4 (H=512)
    const float4 v = ((const float4*)(P + (size_t)r * 512))[t];
    float ss = v.x * v.x + v.y * v.y + v.z * v.z + v.w * v.w;
#pragma unroll
    for (int m = 16; m; m >>= 1) ss += __shfl_xor_sync(0xffffffffu, ss, m);
    __shared__ float ws[4];
    if ((t & 31) == 0) ws[t >> 5] = ss;
    __syncthreads();
    const float d = fmaxf(sqrtf(ws[0] + ws[1] + ws[2] + ws[3]), 1e-12f);
    uint32_t hp[2];
    hp[0] = pack_h2(v.x / d, v.y / d);
    hp[1] = pack_h2(v.z / d, v.w / d);
    __half* dst = isQ ? Qh : Kh;
    *(uint2*)(dst + (size_t)r * 512 + t * 4) = make_uint2(hp[0], hp[1]);
    if (isQ && t == 0) den[r] = 0.f;
}

// ------------------------- launch -------------------------------------------
extern "C" void kernel_launch(void* const* d_in, const int* in_sizes, int n_in,
                              void* d_out, int out_size)
{
    const float* x       = (const float*)d_in[0];
    const float* anchors = (const float*)d_in[1];
    const float* Wq      = (const float*)d_in[2];
    const float* Wk      = (const float*)d_in[3];
    const float* values  = (const float*)d_in[4];
    float* out = (float*)d_out;

    const int D = 512, H = 512;
    const int B = in_sizes[0] / D;   // 16384
    const int A = in_sizes[1] / D;   // 4096

    float *Qf, *Kf, *dn;
    __nv_bfloat16 *xhi, *xlo, *ahi, *alo, *Wqthi, *Wqtlo, *Wkthi, *Wktlo;
    __half *Qh, *Kh, *E, *Vt;
    cudaGetSymbolAddress((void**)&Qf,    g_Qf);
    cudaGetSymbolAddress((void**)&Kf,    g_Kf);
    cudaGetSymbolAddress((void**)&dn,    g_den);
    cudaGetSymbolAddress((void**)&xhi,   g_xhi);
    cudaGetSymbolAddress((void**)&xlo,   g_xlo);
    cudaGetSymbolAddress((void**)&ahi,   g_ahi);
    cudaGetSymbolAddress((void**)&alo,   g_alo);
    cudaGetSymbolAddress((void**)&Wqthi, g_Wqthi);
    cudaGetSymbolAddress((void**)&Wqtlo, g_Wqtlo);
    cudaGetSymbolAddress((void**)&Wkthi, g_Wkthi);
    cudaGetSymbolAddress((void**)&Wktlo, g_Wktlo);
    cudaGetSymbolAddress((void**)&Qh,    g_Qh);
    cudaGetSymbolAddress((void**)&Kh,    g_Kh);
    cudaGetSymbolAddress((void**)&E,     g_E);
    cudaGetSymbolAddress((void**)&Vt,    g_Vt);

    cudaFuncSetAttribute(proj3_dual_kernel,
                         cudaFuncAttributeMaxDynamicSharedMemorySize, SMEM4);
    cudaFuncSetAttribute(sim1_kernel,
                         cudaFuncAttributeMaxDynamicSharedMemorySize, SMEM2T);
    cudaFuncSetAttribute(out1_kernel,
                         cudaFuncAttributeMaxDynamicSharedMemorySize, SMEM2T);

    // 1) input splits + all transposes (two launches)
    const int n4x = B * D / 4, n4a = A * D / 4;
    split_dual_kernel<<<(n4x + n4a + 255) / 256, 256>>>(
        x, xhi, xlo, n4x, anchors, ahi, alo, n4a);
    trans_all_kernel<<<dim3(16, 16 + 16 + A / 32), dim3(32, 8)>>>(
        Wq, Wqthi, Wqtlo, Wk, Wkthi, Wktlo, values, Vt);

    // 2) both projections in one launch
    proj3_dual_kernel<<<dim3(H / 128, B / 128 + A / 128), 256, SMEM4>>>(
        xhi, xlo, Wqthi, Wqtlo, Qf,
        ahi, alo, Wkthi, Wktlo, Kf,
        B / 128, D, H);

    // 3) merged l2 normalize (Q fp16 + den=0; K fp16)
    l2norm_dual_kernel<<<B + A, 128>>>(Qf, Qh, dn, B, Kf, Kh);

    // 4) SIM: E = exp(quant(Qh @ Kh^T)) fp16, den = rowsum (1-term fp16)
    sim1_kernel<<<dim3(A / 128, B / 128), 256, SMEM2T>>>(
        Qh, Kh, H, A, dn, E);

    // 5) OUT: out = (E @ V) / den  (1-term fp16)
    out1_kernel<<<dim3(H / 128, B / 128), 256, SMEM2T>>>(
        E, Vt, A, H, dn, out);
}